// round 2
// baseline (speedup 1.0000x reference)
#include <cuda_runtime.h>
#include <cstdint>

// ============================================================================
// Problem constants
// ============================================================================
static constexpr int EDGES_MAX = 65536;

// Scratch for c_Q / c_KV (fp32), [E, 512] each (raw GEMM out, LN'd in place).
__device__ float g_cQ [(size_t)EDGES_MAX * 512];
__device__ float g_cKV[(size_t)EDGES_MAX * 512];

// SMEM geometry: per stage, A tile 128x32 fp32 + B tile 128x32 fp32,
// rows padded to stride 36 floats (144B, 16B-multiple for cp.async, and
// conflict-free LDS fragment access: bank = (row*4 + tig + 8k) mod 32).
static constexpr int LDK       = 36;                  // floats per row
static constexpr int TILE_F    = 128 * LDK;           // 4608 floats per tile
static constexpr int STAGE_F   = 2 * TILE_F;          // 9216 floats (A then B)
static constexpr int STAGES    = 3;
static constexpr int PIPE_F    = STAGES * STAGE_F;    // 27648 floats = 110592 B
static constexpr int ROPE_F    = 128 * 16 * 2;        // float2 table
static constexpr int SMEM_K1   = PIPE_F * 4;                  // 110592 B
static constexpr int SMEM_K3   = (PIPE_F + ROPE_F) * 4;       // 126976 B

// ============================================================================
// PTX helpers (sm_103-plain only: NO tcgen05 / TMEM)
// ============================================================================
__device__ __forceinline__ uint32_t smem_to_u32(const void* p) {
    uint32_t a;
    asm("{ .reg .u64 t; cvta.to.shared.u64 t, %1; cvt.u32.u64 %0, t; }" : "=r"(a) : "l"(p));
    return a;
}

#define CP_ASYNC16(dst_u32, src_ptr) \
    asm volatile("cp.async.cg.shared.global [%0], [%1], 16;" :: "r"(dst_u32), "l"(src_ptr))
#define CP_COMMIT() asm volatile("cp.async.commit_group;" ::: "memory")
#define CP_WAIT1()  asm volatile("cp.async.wait_group 1;"  ::: "memory")

// Round fp32 -> tf32 (rna removes the truncation bias of the HW read path).
__device__ __forceinline__ uint32_t f2tf32(float x) {
    uint32_t u;
    asm("cvt.rna.tf32.f32 %0, %1;" : "=r"(u) : "f"(x));
    return u;
}

// m16n8k8 tf32 mma, D += A*B, fp32 accum.
__device__ __forceinline__ void mma8(float& d0, float& d1, float& d2, float& d3,
                                     uint32_t a0, uint32_t a1, uint32_t a2, uint32_t a3,
                                     uint32_t b0, uint32_t b1) {
    asm volatile(
        "mma.sync.aligned.m16n8k8.row.col.f32.tf32.tf32.f32 "
        "{%0,%1,%2,%3}, {%4,%5,%6,%7}, {%8,%9}, {%0,%1,%2,%3};"
        : "+f"(d0), "+f"(d1), "+f"(d2), "+f"(d3)
        : "r"(a0), "r"(a1), "r"(a2), "r"(a3), "r"(b0), "r"(b1));
}

// ============================================================================
// cp.async tile loader: 128 rows x 32 floats (8 x 16B per row) into padded smem.
// 256 threads, 4 x 16B each.
// ============================================================================
__device__ __forceinline__ void load_tile(uint32_t dst_u32, const float* __restrict__ src,
                                          long ld, int tid) {
    #pragma unroll
    for (int i = 0; i < 4; i++) {
        int idx = tid + i * 256;
        int row = idx >> 3, q = idx & 7;
        uint32_t d = dst_u32 + (uint32_t)(row * LDK + q * 4) * 4u;
        CP_ASYNC16(d, src + (size_t)row * ld + q * 4);
    }
}

// ============================================================================
// Core: C[128,128] = A[128,K] * W[128,K]^T, 3-stage cp.async pipeline,
// 8 warps in 4(M) x 2(N) grid, warp tile 32x64, per-thread accum 2x8x4.
// Optional split A (concat along K at chunk index asplit) and RoPE epilogue.
// ============================================================================
__device__ void gemm128(const float* __restrict__ A0, const float* __restrict__ A1,
                        int asplit, long lda,
                        const float* __restrict__ W, long ldw, int nch,
                        float* __restrict__ outp, long ldo, int colbase,
                        int rope, const float* __restrict__ lts,
                        const float* __restrict__ t, long e0)
{
    extern __shared__ float smem[];
    const uint32_t su = smem_to_u32(smem);
    const int tid = threadIdx.x;
    const int lane = tid & 31, gid = lane >> 2, tig = lane & 3;
    const int wid = tid >> 5;
    const int wm = wid & 3, wn = wid >> 2;

    float2* ropeTab = reinterpret_cast<float2*>(smem + PIPE_F);
    if (rope) {
        for (int idx = tid; idx < 128 * 16; idx += 256) {
            int row = idx >> 4, j = idx & 15;
            float ang = __ldg(t + e0 + row) / expf(__ldg(lts + j));
            float s, c;
            sincosf(ang, &s, &c);
            ropeTab[idx] = make_float2(c, s);
        }
        // ordered before use by the pipeline's first __syncthreads()
    }

    float acc[2][8][4];
    #pragma unroll
    for (int a = 0; a < 2; a++)
        #pragma unroll
        for (int b = 0; b < 8; b++)
            #pragma unroll
            for (int c = 0; c < 4; c++) acc[a][b][c] = 0.f;

    auto a_src = [&](int c) -> const float* {
        return (c < asplit) ? (A0 + (size_t)c * 32) : (A1 + (size_t)(c - asplit) * 32);
    };

    // prologue: stages 0,1
    load_tile(su, a_src(0), lda, tid);
    load_tile(su + TILE_F * 4, W, ldw, tid);
    CP_COMMIT();
    if (nch > 1) {
        load_tile(su + STAGE_F * 4, a_src(1), lda, tid);
        load_tile(su + (STAGE_F + TILE_F) * 4, W + 32, ldw, tid);
    }
    CP_COMMIT();

    for (int c = 0; c < nch; c++) {
        const int st = c % STAGES;
        CP_WAIT1();
        __syncthreads();
        if (c + 2 < nch) {
            const int s2 = (c + 2) % STAGES;
            load_tile(su + (uint32_t)(s2 * STAGE_F) * 4, a_src(c + 2), lda, tid);
            load_tile(su + (uint32_t)(s2 * STAGE_F + TILE_F) * 4, W + (size_t)(c + 2) * 32, ldw, tid);
        }
        CP_COMMIT();

        const float* As = smem + st * STAGE_F;
        const float* Bs = As + TILE_F;
        #pragma unroll
        for (int ks = 0; ks < 4; ks++) {
            uint32_t af[2][4];
            #pragma unroll
            for (int mf = 0; mf < 2; mf++) {
                const float* ap = As + (wm * 32 + mf * 16 + gid) * LDK + ks * 8 + tig;
                af[mf][0] = f2tf32(ap[0]);
                af[mf][1] = f2tf32(ap[8 * LDK]);
                af[mf][2] = f2tf32(ap[4]);
                af[mf][3] = f2tf32(ap[8 * LDK + 4]);
            }
            #pragma unroll
            for (int nf = 0; nf < 8; nf++) {
                const float* bp = Bs + (wn * 64 + nf * 8 + gid) * LDK + ks * 8 + tig;
                uint32_t b0 = f2tf32(bp[0]);
                uint32_t b1 = f2tf32(bp[4]);
                mma8(acc[0][nf][0], acc[0][nf][1], acc[0][nf][2], acc[0][nf][3],
                     af[0][0], af[0][1], af[0][2], af[0][3], b0, b1);
                mma8(acc[1][nf][0], acc[1][nf][1], acc[1][nf][2], acc[1][nf][3],
                     af[1][0], af[1][1], af[1][2], af[1][3], b0, b1);
            }
        }
    }

    // epilogue: c0/c1 = (row gid, cols 2tig/2tig+1); c2/c3 = row gid+8.
    #pragma unroll
    for (int mf = 0; mf < 2; mf++) {
        #pragma unroll
        for (int rr = 0; rr < 2; rr++) {
            const int row = wm * 32 + mf * 16 + rr * 8 + gid;
            float* orow = outp + (size_t)(e0 + row) * ldo + colbase;
            #pragma unroll
            for (int nf = 0; nf < 8; nf++) {
                const int col = wn * 64 + nf * 8 + tig * 2;
                float x0 = acc[mf][nf][rr * 2 + 0];
                float x1 = acc[mf][nf][rr * 2 + 1];
                if (rope) {
                    float2 cs = ropeTab[row * 16 + ((col & 31) >> 1)];
                    float y0 = x0 * cs.x - x1 * cs.y;
                    float y1 = x0 * cs.y + x1 * cs.x;
                    x0 = y0; x1 = y1;
                }
                *reinterpret_cast<float2*>(orow + col) = make_float2(x0, x1);
            }
        }
    }
}

// ============================================================================
// K1: raw down-projections into scratch.
// grid (8, tiles): x = segment (fast, L2 reuse of activation tile), y = M-tile.
// ============================================================================
__global__ void __launch_bounds__(256)
mla_k1(const float* __restrict__ x_src, const float* __restrict__ x_dst,
       const float* __restrict__ edge_emb,
       const float* __restrict__ Wqd, const float* __restrict__ Wkvd)
{
    const int y = blockIdx.x;
    const long e0 = (long)blockIdx.y * 128;
    if (y < 4) {
        gemm128(x_src + e0 * 1024, nullptr, 1 << 30, 1024,
                Wqd + (size_t)y * 128 * 1024, 1024, 32,
                g_cQ, 512, y * 128, 0, nullptr, nullptr, e0);
    } else {
        gemm128(x_dst + e0 * 1024, edge_emb + e0 * 1024, 32, 1024,
                Wkvd + (size_t)(y - 4) * 128 * 2048, 2048, 64,
                g_cKV, 512, (y - 4) * 128, 0, nullptr, nullptr, e0);
    }
}

// ============================================================================
// K2: LayerNorm in place over scratch. One warp per 512-wide row.
// ============================================================================
__global__ void __launch_bounds__(256)
mla_ln(const float* __restrict__ qg, const float* __restrict__ qb,
       const float* __restrict__ kvg, const float* __restrict__ kvb, int E)
{
    const int w = (blockIdx.x * 256 + threadIdx.x) >> 5;   // global row over 2E
    const int lane = threadIdx.x & 31;
    float* base;
    const float *g, *b;
    if (w < E) { base = g_cQ + (size_t)w * 512; g = qg; b = qb; }
    else       { base = g_cKV + (size_t)(w - E) * 512; g = kvg; b = kvb; }

    float4 v[4];
    float s = 0.f, sq = 0.f;
    #pragma unroll
    for (int i = 0; i < 4; i++) {
        v[i] = reinterpret_cast<const float4*>(base)[i * 32 + lane];
        s  += v[i].x + v[i].y + v[i].z + v[i].w;
        sq += v[i].x * v[i].x + v[i].y * v[i].y + v[i].z * v[i].z + v[i].w * v[i].w;
    }
    #pragma unroll
    for (int o = 16; o > 0; o >>= 1) {
        s  += __shfl_xor_sync(0xFFFFFFFFu, s, o);
        sq += __shfl_xor_sync(0xFFFFFFFFu, sq, o);
    }
    const float mean = s * (1.f / 512.f);
    const float var  = sq * (1.f / 512.f) - mean * mean;
    const float rstd = rsqrtf(var + 1e-5f);
    #pragma unroll
    for (int i = 0; i < 4; i++) {
        int fi = i * 32 + lane;
        float4 gv = reinterpret_cast<const float4*>(g)[fi];
        float4 bv = reinterpret_cast<const float4*>(b)[fi];
        float4 o;
        o.x = (v[i].x - mean) * rstd * gv.x + bv.x;
        o.y = (v[i].y - mean) * rstd * gv.y + bv.y;
        o.z = (v[i].z - mean) * rstd * gv.z + bv.z;
        o.w = (v[i].w - mean) * rstd * gv.w + bv.w;
        reinterpret_cast<float4*>(base)[fi] = o;
    }
}

// ============================================================================
// K3: up-projections + fused RoPE. grid (24, tiles): x = N-segment (fast).
// y-map: 0-3 Qn, 4-7 Qr, 8-11 Kn, 12-15 Kr, 16-23 V.
// ============================================================================
__global__ void __launch_bounds__(256)
mla_k3(const float* __restrict__ t,
       const float* __restrict__ Wqn, const float* __restrict__ Wqr,
       const float* __restrict__ Wkn, const float* __restrict__ Wkr,
       const float* __restrict__ Wv,
       const float* __restrict__ qlts, const float* __restrict__ klts,
       float* __restrict__ out, int E)
{
    const int y = blockIdx.x;
    const long e0 = (long)blockIdx.y * 128;
    const long S = (long)E * 512;

    const float* A;
    const float* W;
    float* o;
    long ldo;
    int colbase, rope = 0;
    const float* lts = nullptr;

    if (y < 16) {
        const int seg = y >> 2, nt = y & 3;
        A = (seg < 2 ? g_cQ : g_cKV) + e0 * 512;
        const float* segW = (seg == 0) ? Wqn : (seg == 1) ? Wqr : (seg == 2) ? Wkn : Wkr;
        W = segW + (size_t)nt * 128 * 512;
        o = out + (long)seg * S;
        ldo = 512;
        colbase = nt * 128;
        if (seg == 1) { rope = 1; lts = qlts; }
        if (seg == 3) { rope = 1; lts = klts; }
    } else {
        const int nt = y - 16;
        A = g_cKV + e0 * 512;
        W = Wv + (size_t)nt * 128 * 512;
        o = out + 4 * S;
        ldo = 1024;
        colbase = nt * 128;
    }
    gemm128(A, nullptr, 1 << 30, 512, W, 512, 16, o, ldo, colbase, rope, lts, t, e0);
}

// ============================================================================
// Launch
// ============================================================================
extern "C" void kernel_launch(void* const* d_in, const int* in_sizes, int n_in,
                              void* d_out, int out_size) {
    const float* x_src = (const float*)d_in[0];
    const float* x_dst = (const float*)d_in[1];
    const float* edge  = (const float*)d_in[2];
    const float* t     = (const float*)d_in[3];
    const float* Wqd   = (const float*)d_in[4];
    const float* qg    = (const float*)d_in[5];
    const float* qb    = (const float*)d_in[6];
    const float* Wqn   = (const float*)d_in[7];
    const float* Wqr   = (const float*)d_in[8];
    const float* Wkvd  = (const float*)d_in[9];
    const float* kvg   = (const float*)d_in[10];
    const float* kvb   = (const float*)d_in[11];
    const float* Wkn   = (const float*)d_in[12];
    const float* Wkr   = (const float*)d_in[13];
    const float* Wv    = (const float*)d_in[14];
    const float* qlts  = (const float*)d_in[15];
    const float* klts  = (const float*)d_in[16];
    float* out = (float*)d_out;

    static bool attr_set = false;
    if (!attr_set) {
        cudaFuncSetAttribute(mla_k1, cudaFuncAttributeMaxDynamicSharedMemorySize, SMEM_K1);
        cudaFuncSetAttribute(mla_k3, cudaFuncAttributeMaxDynamicSharedMemorySize, SMEM_K3);
        attr_set = true;
    }

    const int E = in_sizes[3];
    const int tiles = E / 128;

    mla_k1<<<dim3(8, tiles), 256, SMEM_K1>>>(x_src, x_dst, edge, Wqd, Wkvd);
    mla_ln<<<(2 * E) / 8, 256>>>(qg, qb, kvg, kvb, E);
    mla_k3<<<dim3(24, tiles), 256, SMEM_K3>>>(t, Wqn, Wqr, Wkn, Wkr, Wv, qlts, klts, out, E);
}

// round 3
// speedup vs baseline: 2.2223x; 2.2223x over previous
#include <cuda_runtime.h>
#include <cuda_fp16.h>
#include <cstdint>

// ============================================================================
// Problem constants
// ============================================================================
static constexpr int EDGES_MAX = 65536;

// fp16 scratch: [x_src | x_dst | edge_emb], each E*1024
__device__ __align__(16) __half g_xh[(size_t)3 * EDGES_MAX * 1024];
// fp16 weights, concatenated
__device__ __align__(16) __half g_wh[3145728];
// raw GEMM outputs (fp32) and LayerNorm'd fp16 activations
__device__ __align__(16) float  g_cQ  [(size_t)EDGES_MAX * 512];
__device__ __align__(16) float  g_cKV [(size_t)EDGES_MAX * 512];
__device__ __align__(16) __half g_cQh [(size_t)EDGES_MAX * 512];
__device__ __align__(16) __half g_cKVh[(size_t)EDGES_MAX * 512];

// weight offsets in g_wh (elements)
static constexpr size_t OFF_WQD  = 0;
static constexpr size_t OFF_WKVD = OFF_WQD  + (size_t)512 * 1024;   //  524288
static constexpr size_t OFF_WQN  = OFF_WKVD + (size_t)512 * 2048;   // 1572864
static constexpr size_t OFF_WQR  = OFF_WQN  + (size_t)512 * 512;
static constexpr size_t OFF_WKN  = OFF_WQR  + (size_t)512 * 512;
static constexpr size_t OFF_WKR  = OFF_WKN  + (size_t)512 * 512;
static constexpr size_t OFF_WV   = OFF_WKR  + (size_t)512 * 512;    // 2621440

// SMEM: per stage A[128x64 fp16]=16KB + B[128x64 fp16]=16KB, 3 stages.
static constexpr int STAGE_B = 32768;
static constexpr int STAGES  = 3;
static constexpr int PIPE_B  = STAGES * STAGE_B;          // 98304
static constexpr int SMEM_K1 = PIPE_B;
static constexpr int SMEM_K3 = PIPE_B + 128 * 16 * 8;     // + rope float2 table

// ============================================================================
// PTX helpers
// ============================================================================
__device__ __forceinline__ uint32_t smem_to_u32(const void* p) {
    uint32_t a;
    asm("{ .reg .u64 t; cvta.to.shared.u64 t, %1; cvt.u32.u64 %0, t; }" : "=r"(a) : "l"(p));
    return a;
}

#define CP_ASYNC16(dst_u32, src_ptr) \
    asm volatile("cp.async.cg.shared.global [%0], [%1], 16;" :: "r"(dst_u32), "l"(src_ptr))
#define CP_COMMIT() asm volatile("cp.async.commit_group;" ::: "memory")
#define CP_WAIT1()  asm volatile("cp.async.wait_group 1;"  ::: "memory")

__device__ __forceinline__ void ldsm_x4(uint32_t* r, uint32_t addr) {
    asm volatile("ldmatrix.sync.aligned.m8n8.x4.shared.b16 {%0,%1,%2,%3}, [%4];"
                 : "=r"(r[0]), "=r"(r[1]), "=r"(r[2]), "=r"(r[3]) : "r"(addr));
}

__device__ __forceinline__ void mma16816(float* d, const uint32_t* a, uint32_t b0, uint32_t b1) {
    asm volatile(
        "mma.sync.aligned.m16n8k16.row.col.f32.f16.f16.f32 "
        "{%0,%1,%2,%3}, {%4,%5,%6,%7}, {%8,%9}, {%0,%1,%2,%3};"
        : "+f"(d[0]), "+f"(d[1]), "+f"(d[2]), "+f"(d[3])
        : "r"(a[0]), "r"(a[1]), "r"(a[2]), "r"(a[3]), "r"(b0), "r"(b1));
}

// ============================================================================
// fp16 tile loader: 128 rows x 64 halves (128B/row), XOR-16B swizzle.
// 256 threads, 4 x 16B each.
// ============================================================================
__device__ __forceinline__ void load_tile_h(uint32_t dst, const __half* __restrict__ src,
                                            long ld, int tid) {
    #pragma unroll
    for (int i = 0; i < 4; i++) {
        int idx = tid + i * 256;
        int row = idx >> 3, c = idx & 7;
        uint32_t d = dst + (uint32_t)(row * 128 + ((c ^ (row & 7)) << 4));
        CP_ASYNC16(d, src + (size_t)row * ld + c * 8);
    }
}

// ============================================================================
// Core: C[128,128] = A[128,K] * W[128,K]^T (fp16 in, fp32 accum/out)
// 8 warps 4(M) x 2(N), warp tile 32x64, K consumed in chunks of 64.
// ============================================================================
__device__ void gemm_h(const __half* __restrict__ A0, const __half* __restrict__ A1,
                       int asplit, long lda,
                       const __half* __restrict__ W, long ldw, int nch,
                       float* __restrict__ outp, long ldo, int colbase,
                       int rope, const float* __restrict__ lts,
                       const float* __restrict__ t, long e0)
{
    extern __shared__ char smem[];
    const uint32_t su = smem_to_u32(smem);
    const int tid  = threadIdx.x;
    const int lane = tid & 31;
    const int wid  = tid >> 5, wm = wid & 3, wn = wid >> 2;
    const int l7   = lane & 7, sub = lane >> 3;
    const int khi  = sub >> 1;     // which 16B k-half this lane addresses
    const int rsel = (sub & 1) * 8;

    float2* ropeTab = reinterpret_cast<float2*>(smem + PIPE_B);
    if (rope) {
        for (int idx = tid; idx < 128 * 16; idx += 256) {
            int row = idx >> 4, j = idx & 15;
            float ang = __ldg(t + e0 + row) / expf(__ldg(lts + j));
            float s, c;
            sincosf(ang, &s, &c);
            ropeTab[idx] = make_float2(c, s);
        }
    }

    float acc[2][8][4];
    #pragma unroll
    for (int a = 0; a < 2; a++)
        #pragma unroll
        for (int b = 0; b < 8; b++)
            #pragma unroll
            for (int c = 0; c < 4; c++) acc[a][b][c] = 0.f;

    // precomputed ldmatrix row bases (byte offset within tile) + swizzle key
    uint32_t abase[2]; uint32_t a7[2];
    #pragma unroll
    for (int mf = 0; mf < 2; mf++) {
        int r = wm * 32 + mf * 16 + rsel + l7;
        a7[mf] = (uint32_t)(r & 7);
        abase[mf] = (uint32_t)(r * 128);
    }
    uint32_t bbase[4]; uint32_t b7[4];
    #pragma unroll
    for (int np = 0; np < 4; np++) {
        int r = wn * 64 + np * 16 + rsel + l7;
        b7[np] = (uint32_t)(r & 7);
        bbase[np] = (uint32_t)(r * 128);
    }

    auto a_src = [&](int c) -> const __half* {
        return (c < asplit) ? (A0 + (size_t)c * 64) : (A1 + (size_t)(c - asplit) * 64);
    };

    // prologue: stages 0,1
    load_tile_h(su, a_src(0), lda, tid);
    load_tile_h(su + 16384, W, ldw, tid);
    CP_COMMIT();
    if (nch > 1) {
        load_tile_h(su + STAGE_B, a_src(1), lda, tid);
        load_tile_h(su + STAGE_B + 16384, W + 64, ldw, tid);
    }
    CP_COMMIT();

    for (int c = 0; c < nch; c++) {
        const int st = c % STAGES;
        CP_WAIT1();
        __syncthreads();
        if (c + 2 < nch) {
            const int s2 = (c + 2) % STAGES;
            load_tile_h(su + (uint32_t)(s2 * STAGE_B), a_src(c + 2), lda, tid);
            load_tile_h(su + (uint32_t)(s2 * STAGE_B + 16384), W + (size_t)(c + 2) * 64, ldw, tid);
        }
        CP_COMMIT();

        const uint32_t As = su + st * STAGE_B;
        const uint32_t Bs = As + 16384;
        #pragma unroll
        for (int ks = 0; ks < 4; ks++) {
            const uint32_t kb = (uint32_t)(ks * 2 + khi);
            uint32_t af[2][4];
            #pragma unroll
            for (int mf = 0; mf < 2; mf++)
                ldsm_x4(af[mf], As + abase[mf] + ((kb ^ a7[mf]) << 4));
            uint32_t bq[4][4];
            #pragma unroll
            for (int np = 0; np < 4; np++)
                ldsm_x4(bq[np], Bs + bbase[np] + ((kb ^ b7[np]) << 4));
            #pragma unroll
            for (int mf = 0; mf < 2; mf++)
                #pragma unroll
                for (int np = 0; np < 4; np++) {
                    mma16816(acc[mf][np * 2 + 0], af[mf], bq[np][0], bq[np][2]);
                    mma16816(acc[mf][np * 2 + 1], af[mf], bq[np][1], bq[np][3]);
                }
        }
    }

    // epilogue: c0/c1 = (row gid, col 2tig / 2tig+1); c2/c3 = row gid+8.
    const int gid = lane >> 2, tig = lane & 3;
    #pragma unroll
    for (int mf = 0; mf < 2; mf++) {
        #pragma unroll
        for (int rr = 0; rr < 2; rr++) {
            const int row = wm * 32 + mf * 16 + rr * 8 + gid;
            float* orow = outp + (size_t)(e0 + row) * ldo + colbase;
            #pragma unroll
            for (int nf = 0; nf < 8; nf++) {
                const int col = wn * 64 + nf * 8 + tig * 2;
                float x0 = acc[mf][nf][rr * 2 + 0];
                float x1 = acc[mf][nf][rr * 2 + 1];
                if (rope) {
                    float2 cs = ropeTab[row * 16 + ((col & 31) >> 1)];
                    float y0 = x0 * cs.x - x1 * cs.y;
                    float y1 = x0 * cs.y + x1 * cs.x;
                    x0 = y0; x1 = y1;
                }
                *reinterpret_cast<float2*>(orow + col) = make_float2(x0, x1);
            }
        }
    }
}

// ============================================================================
// Prepass: fp32 -> fp16 (rn), 8 elems/thread, 16B stores.
// ============================================================================
__global__ void __launch_bounds__(256)
cvt_f2h(const float* __restrict__ s, __half* __restrict__ d, long n)
{
    long i = ((long)blockIdx.x * 256 + threadIdx.x) * 8;
    if (i >= n) return;
    float4 v0 = *reinterpret_cast<const float4*>(s + i);
    float4 v1 = *reinterpret_cast<const float4*>(s + i + 4);
    __half2 h[4];
    h[0] = __floats2half2_rn(v0.x, v0.y);
    h[1] = __floats2half2_rn(v0.z, v0.w);
    h[2] = __floats2half2_rn(v1.x, v1.y);
    h[3] = __floats2half2_rn(v1.z, v1.w);
    *reinterpret_cast<uint4*>(d + i) = *reinterpret_cast<uint4*>(h);
}

// ============================================================================
// K1: raw down-projections into fp32 scratch.
// grid (8, tiles): x = N-segment (fast axis -> L2 reuse of the A tile).
// ============================================================================
__global__ void __launch_bounds__(256, 2)
mla_k1(int E)
{
    const int y = blockIdx.x;
    const long e0 = (long)blockIdx.y * 128;
    const __half* xs = g_xh;
    const __half* xd = g_xh + (size_t)E * 1024;
    const __half* xe = g_xh + (size_t)2 * E * 1024;
    if (y < 4) {
        gemm_h(xs + e0 * 1024, nullptr, 1 << 30, 1024,
               g_wh + OFF_WQD + (size_t)y * 128 * 1024, 1024, 16,
               g_cQ, 512, y * 128, 0, nullptr, nullptr, e0);
    } else {
        gemm_h(xd + e0 * 1024, xe + e0 * 1024, 16, 1024,
               g_wh + OFF_WKVD + (size_t)(y - 4) * 128 * 2048, 2048, 32,
               g_cKV, 512, (y - 4) * 128, 0, nullptr, nullptr, e0);
    }
}

// ============================================================================
// K2: LayerNorm (fp32 scratch -> fp16 activations). One warp per row.
// ============================================================================
__global__ void __launch_bounds__(256)
mla_ln(const float* __restrict__ qg, const float* __restrict__ qb,
       const float* __restrict__ kvg, const float* __restrict__ kvb, int E)
{
    const int w = (blockIdx.x * 256 + threadIdx.x) >> 5;
    const int lane = threadIdx.x & 31;
    const float* base;
    __half* hbase;
    const float *g, *b;
    if (w < E) { base = g_cQ  + (size_t)w * 512;       hbase = g_cQh  + (size_t)w * 512;       g = qg;  b = qb; }
    else       { base = g_cKV + (size_t)(w - E) * 512; hbase = g_cKVh + (size_t)(w - E) * 512; g = kvg; b = kvb; }

    float4 v[4];
    float s = 0.f, sq = 0.f;
    #pragma unroll
    for (int i = 0; i < 4; i++) {
        v[i] = reinterpret_cast<const float4*>(base)[i * 32 + lane];
        s  += v[i].x + v[i].y + v[i].z + v[i].w;
        sq += v[i].x * v[i].x + v[i].y * v[i].y + v[i].z * v[i].z + v[i].w * v[i].w;
    }
    #pragma unroll
    for (int o = 16; o > 0; o >>= 1) {
        s  += __shfl_xor_sync(0xFFFFFFFFu, s, o);
        sq += __shfl_xor_sync(0xFFFFFFFFu, sq, o);
    }
    const float mean = s * (1.f / 512.f);
    const float var  = sq * (1.f / 512.f) - mean * mean;
    const float rstd = rsqrtf(var + 1e-5f);
    __half2* hrow = reinterpret_cast<__half2*>(hbase);
    #pragma unroll
    for (int i = 0; i < 4; i++) {
        int fi = i * 32 + lane;
        float4 gv = reinterpret_cast<const float4*>(g)[fi];
        float4 bv = reinterpret_cast<const float4*>(b)[fi];
        float ox = (v[i].x - mean) * rstd * gv.x + bv.x;
        float oy = (v[i].y - mean) * rstd * gv.y + bv.y;
        float oz = (v[i].z - mean) * rstd * gv.z + bv.z;
        float ow = (v[i].w - mean) * rstd * gv.w + bv.w;
        hrow[i * 64 + lane * 2 + 0] = __floats2half2_rn(ox, oy);
        hrow[i * 64 + lane * 2 + 1] = __floats2half2_rn(oz, ow);
    }
}

// ============================================================================
// K3: up-projections + fused RoPE. grid (24, tiles): x = segment (fast).
// ============================================================================
__global__ void __launch_bounds__(256, 2)
mla_k3(const float* __restrict__ t,
       const float* __restrict__ qlts, const float* __restrict__ klts,
       float* __restrict__ out, int E)
{
    const int y = blockIdx.x;
    const long e0 = (long)blockIdx.y * 128;
    const long S = (long)E * 512;

    const __half* A;
    const __half* W;
    float* o;
    long ldo;
    int colbase, rope = 0;
    const float* lts = nullptr;

    if (y < 16) {
        const int seg = y >> 2, nt = y & 3;
        A = ((seg < 2) ? g_cQh : g_cKVh) + e0 * 512;
        const size_t offs[4] = { OFF_WQN, OFF_WQR, OFF_WKN, OFF_WKR };
        W = g_wh + offs[seg] + (size_t)nt * 128 * 512;
        o = out + (long)seg * S;
        ldo = 512;
        colbase = nt * 128;
        if (seg == 1) { rope = 1; lts = qlts; }
        if (seg == 3) { rope = 1; lts = klts; }
    } else {
        const int nt = y - 16;
        A = g_cKVh + e0 * 512;
        W = g_wh + OFF_WV + (size_t)nt * 128 * 512;
        o = out + 4 * S;
        ldo = 1024;
        colbase = nt * 128;
    }
    gemm_h(A, nullptr, 1 << 30, 512, W, 512, 8, o, ldo, colbase, rope, lts, t, e0);
}

// ============================================================================
// Launch
// ============================================================================
extern "C" void kernel_launch(void* const* d_in, const int* in_sizes, int n_in,
                              void* d_out, int out_size) {
    const float* x_src = (const float*)d_in[0];
    const float* x_dst = (const float*)d_in[1];
    const float* edge  = (const float*)d_in[2];
    const float* t     = (const float*)d_in[3];
    const float* Wqd   = (const float*)d_in[4];
    const float* qg    = (const float*)d_in[5];
    const float* qb    = (const float*)d_in[6];
    const float* Wqn   = (const float*)d_in[7];
    const float* Wqr   = (const float*)d_in[8];
    const float* Wkvd  = (const float*)d_in[9];
    const float* kvg   = (const float*)d_in[10];
    const float* kvb   = (const float*)d_in[11];
    const float* Wkn   = (const float*)d_in[12];
    const float* Wkr   = (const float*)d_in[13];
    const float* Wv    = (const float*)d_in[14];
    const float* qlts  = (const float*)d_in[15];
    const float* klts  = (const float*)d_in[16];
    float* out = (float*)d_out;

    static bool attr_set = false;
    if (!attr_set) {
        cudaFuncSetAttribute(mla_k1, cudaFuncAttributeMaxDynamicSharedMemorySize, SMEM_K1);
        cudaFuncSetAttribute(mla_k3, cudaFuncAttributeMaxDynamicSharedMemorySize, SMEM_K3);
        attr_set = true;
    }

    const int E = in_sizes[3];
    const long EX = (long)E * 1024;

    __half* xh; cudaGetSymbolAddress((void**)&xh, g_xh);
    __half* wh; cudaGetSymbolAddress((void**)&wh, g_wh);

    // prepass: fp32 -> fp16
    cvt_f2h<<<(unsigned)(EX / 2048), 256>>>(x_src, xh, EX);
    cvt_f2h<<<(unsigned)(EX / 2048), 256>>>(x_dst, xh + EX, EX);
    cvt_f2h<<<(unsigned)(EX / 2048), 256>>>(edge,  xh + 2 * EX, EX);
    cvt_f2h<<<256, 256>>>(Wqd,  wh + OFF_WQD,  512L * 1024);
    cvt_f2h<<<512, 256>>>(Wkvd, wh + OFF_WKVD, 512L * 2048);
    cvt_f2h<<<128, 256>>>(Wqn,  wh + OFF_WQN,  512L * 512);
    cvt_f2h<<<128, 256>>>(Wqr,  wh + OFF_WQR,  512L * 512);
    cvt_f2h<<<128, 256>>>(Wkn,  wh + OFF_WKN,  512L * 512);
    cvt_f2h<<<128, 256>>>(Wkr,  wh + OFF_WKR,  512L * 512);
    cvt_f2h<<<256, 256>>>(Wv,   wh + OFF_WV,   512L * 512 * 2);

    const int tiles = E / 128;
    mla_k1<<<dim3(8, tiles), 256, SMEM_K1>>>(E);
    mla_ln<<<(2 * E) / 8, 256>>>(qg, qb, kvg, kvb, E);
    mla_k3<<<dim3(24, tiles), 256, SMEM_K3>>>(t, qlts, klts, out, E);
}